// round 11
// baseline (speedup 1.0000x reference)
#include <cuda_runtime.h>
#include <stdint.h>

#define BB 256
#define TT 32768
#define KK 3
#define ALPHA 0.95f
#define THETA 0.05f
#define LCH 256          // chunk length
#define NCH (TT / LCH)   // 128 chunks
#define WMAX 512         // max warmup steps
#define WS 16            // scan window steps
#define ROWS 384         // 128 b x 3 k rows per scan block
#define RPAD 20          // padded smem row length (floats); stride 15 quad-banks
#define NBUF 3           // smem ring depth

// ---------------------------------------------------------------------------
// Kernel 1: causal convs. Tile = 32 b x 64 t, 256 threads, 8 outputs/thread.
// Writes u ONLY to d_out [b][k][t]. FMA accumulation order identical to
// validated R3-R10 kernels (bit-identical u -> identical spikes).
// ---------------------------------------------------------------------------
__global__ void __launch_bounds__(256) conv_kernel(const float* __restrict__ x,
                                                   const float* __restrict__ w8,
                                                   const float* __restrict__ w16,
                                                   const float* __restrict__ w32,
                                                   float* __restrict__ u_out) {
    __shared__ float wf[64];   // flipped weights: [0:32)=w32, [32:48)=w16, [48:56)=w8
    __shared__ __align__(16) float buf[KK * 32 * 69];
    float (*xs)[100]    = reinterpret_cast<float (*)[100]>(buf);     // 32 x 100
    float (*us)[32][69] = reinterpret_cast<float (*)[32][69]>(buf);  // 3 x 32 x 69

    const int tid    = threadIdx.x;
    const int w      = tid >> 5;
    const int l      = tid & 31;
    const int tile_t = blockIdx.x * 64;
    const int b0     = blockIdx.y * 32;

    if (tid < 32)       wf[tid] = w32[31 - tid];
    else if (tid < 48)  wf[tid] = w16[47 - tid];
    else if (tid < 56)  wf[tid] = w8[55 - tid];

    // phase A (vectorized): xs[r][4*c4..] = x[b0+r][tile_t-32+4*c4..]
    {
        const int r  = 4 * w + (l >> 3);
        const int c4 = l & 7;
        const float4* xrow = (const float4*)(x + (size_t)(b0 + r) * TT + tile_t - 32);
        float4* xsrow = (float4*)&xs[r][0];
        if (tile_t == 0) {
            xsrow[c4] = make_float4(0.f, 0.f, 0.f, 0.f);   // left halo = zeros
        } else {
            xsrow[c4] = xrow[c4];
        }
        xsrow[c4 + 8]  = xrow[c4 + 8];
        xsrow[c4 + 16] = xrow[c4 + 16];
    }
    __syncthreads();

    // phase B: 8 outputs per thread; window via 10 LDS.128
    const int bl = l;
    const int tq = w * 8;
    float win[40];                      // win[i] = x[tile_t + tq + i - 32]
    {
        const float4* wrow = (const float4*)&xs[bl][tq];
#pragma unroll
        for (int i4 = 0; i4 < 10; i4++) {
            float4 v = wrow[i4];
            win[4 * i4 + 0] = v.x;
            win[4 * i4 + 1] = v.y;
            win[4 * i4 + 2] = v.z;
            win[4 * i4 + 3] = v.w;
        }
    }
    __syncthreads();   // xs dead; union reused as us

    float a32[8] = {0,0,0,0,0,0,0,0}, a16[8] = {0,0,0,0,0,0,0,0}, a8[8] = {0,0,0,0,0,0,0,0};
#pragma unroll
    for (int d = 0; d < 32; d++) {
        float wv = wf[d];
#pragma unroll
        for (int j = 0; j < 8; j++) a32[j] = fmaf(wv, win[32 + j - d], a32[j]);
    }
#pragma unroll
    for (int d = 0; d < 16; d++) {
        float wv = wf[32 + d];
#pragma unroll
        for (int j = 0; j < 8; j++) a16[j] = fmaf(wv, win[32 + j - d], a16[j]);
    }
#pragma unroll
    for (int d = 0; d < 8; d++) {
        float wv = wf[48 + d];
#pragma unroll
        for (int j = 0; j < 8; j++) a8[j] = fmaf(wv, win[32 + j - d], a8[j]);
    }
#pragma unroll
    for (int j = 0; j < 8; j++) {
        us[0][bl][tq + j] = a8[j];
        us[1][bl][tq + j] = a16[j];
        us[2][bl][tq + j] = a32[j];
    }
    __syncthreads();

    // phase D: u_out [b][k][t] (warp writes 128B rows)
#pragma unroll
    for (int bbq = 0; bbq < 4; bbq++) {
        int bb = w * 4 + bbq;
        float* orow = u_out + (size_t)(b0 + bb) * 3 * TT + tile_t;
#pragma unroll
        for (int k = 0; k < 3; k++)
#pragma unroll
            for (int h = 0; h < 2; h++)
                orow[(size_t)k * TT + 32 * h + l] = us[k][bb][32 * h + l];
    }
}

// ---------------------------------------------------------------------------
// Kernel 2: chunked WTA-LIF scan reading u_out directly via cp.async-staged
// smem transpose. Window = 16 steps: tile [384 rows][64B] -> smem ring (3 bufs,
// row pad 20 floats = conflict-free LDS.128). wait_group 2 => 32-step distance.
// Spike masks: uint16 per window per (k,b). Fused expansion at block end.
// ---------------------------------------------------------------------------
__device__ __forceinline__ void lif_step(float& v0, float& v1, float& v2,
                                         float u0, float u1, float u2,
                                         bool& s0, bool& s1, bool& s2) {
    v0 = fmaf(ALPHA, v0, u0);
    v1 = fmaf(ALPHA, v1, u1);
    v2 = fmaf(ALPHA, v2, u2);
    // winner-take-all, argmax first-index tie-break, spike iff winner >= theta
    s0 = (v0 >= v1) & (v0 >= v2) & (v0 >= THETA);
    s1 = (v1 >  v0) & (v1 >= v2) & (v1 >= THETA);
    s2 = (v2 >  v0) & (v2 >  v1) & (v2 >= THETA);
    v0 = s0 ? v0 - THETA : v0;
    v1 = s1 ? v1 - THETA : v1;
    v2 = s2 ? v2 - THETA : v2;
}

extern __shared__ __align__(16) unsigned char smem_raw[];

__global__ void __launch_bounds__(128) scan_kernel(const float* __restrict__ u,
                                                   float* __restrict__ out_s) {
    float*    ub   = (float*)smem_raw;                                 // [NBUF][ROWS][RPAD]
    uint16_t* sb16 = (uint16_t*)(smem_raw + (size_t)NBUF * ROWS * RPAD * 4); // [KK][16][128]

    const int tid    = threadIdx.x;
    const int b0s    = (blockIdx.x & 1) * 128;
    const int c      = blockIdx.x >> 1;
    const int out_t0 = c * LCH;
    const int t0     = (out_t0 > WMAX) ? (out_t0 - WMAX) : 0;
    const int nw     = out_t0 - t0;        // warmup steps (0, 256, or 512)
    const int nww    = nw / WS;            // warmup windows
    const int nwT    = nww + LCH / WS;     // total windows

    const float* gbase = u + (size_t)b0s * 3 * TT + t0;   // + gr*TT + t

    // --- async producer: load window w's tile into ring slot w%NBUF ---
    auto issue_window = [&](int w) {
        float* dst = ub + (size_t)(w % NBUF) * ROWS * RPAD;
        const int tw = w * WS;
#pragma unroll
        for (int i = 0; i < 12; i++) {
            int e   = tid + 128 * i;       // 0..1535
            int gr  = e >> 2;
            int seg = e & 3;
            const float* src = gbase + (size_t)gr * TT + tw + 4 * seg;
            unsigned sdst = (unsigned)__cvta_generic_to_shared(dst + gr * RPAD + 4 * seg);
            asm volatile("cp.async.ca.shared.global [%0], [%1], 16;\n"
                         :: "r"(sdst), "l"(src) : "memory");
        }
    };

    issue_window(0); asm volatile("cp.async.commit_group;\n" ::: "memory");
    issue_window(1); asm volatile("cp.async.commit_group;\n" ::: "memory");
    issue_window(2); asm volatile("cp.async.commit_group;\n" ::: "memory");

    float v0 = 0.f, v1 = 0.f, v2 = 0.f;
    bool s0, s1, s2;

    for (int w = 0; w < nwT; w++) {
        asm volatile("cp.async.wait_group 2;\n" ::: "memory");
        __syncthreads();

        const float* r0 = ub + (size_t)(w % NBUF) * ROWS * RPAD + (size_t)tid * 3 * RPAD;
        const int mainw = w - nww;
        if (mainw < 0) {
            // warmup window: no spike recording
#pragma unroll
            for (int g = 0; g < 4; g++) {
                float4 a  = *(const float4*)(r0 + 4 * g);
                float4 bq = *(const float4*)(r0 + RPAD + 4 * g);
                float4 cq = *(const float4*)(r0 + 2 * RPAD + 4 * g);
                lif_step(v0, v1, v2, a.x, bq.x, cq.x, s0, s1, s2);
                lif_step(v0, v1, v2, a.y, bq.y, cq.y, s0, s1, s2);
                lif_step(v0, v1, v2, a.z, bq.z, cq.z, s0, s1, s2);
                lif_step(v0, v1, v2, a.w, bq.w, cq.w, s0, s1, s2);
            }
        } else {
            uint32_t m0 = 0, m1 = 0, m2 = 0;
#pragma unroll
            for (int g = 0; g < 4; g++) {
                float4 a  = *(const float4*)(r0 + 4 * g);
                float4 bq = *(const float4*)(r0 + RPAD + 4 * g);
                float4 cq = *(const float4*)(r0 + 2 * RPAD + 4 * g);
#pragma unroll
                for (int j = 0; j < 4; j++) {
                    float u0 = (j == 0) ? a.x  : (j == 1) ? a.y  : (j == 2) ? a.z  : a.w;
                    float u1 = (j == 0) ? bq.x : (j == 1) ? bq.y : (j == 2) ? bq.z : bq.w;
                    float u2 = (j == 0) ? cq.x : (j == 1) ? cq.y : (j == 2) ? cq.z : cq.w;
                    lif_step(v0, v1, v2, u0, u1, u2, s0, s1, s2);
                    const uint32_t bit = 1u << (g * 4 + j);
                    if (s0) m0 |= bit;
                    if (s1) m1 |= bit;
                    if (s2) m2 |= bit;
                }
            }
            sb16[(0 * 16 + mainw) * 128 + tid] = (uint16_t)m0;
            sb16[(1 * 16 + mainw) * 128 + tid] = (uint16_t)m1;
            sb16[(2 * 16 + mainw) * 128 + tid] = (uint16_t)m2;
        }
        __syncthreads();   // all consumers done with slot w%NBUF before reuse

        if (w + NBUF < nwT) issue_window(w + NBUF);
        asm volatile("cp.async.commit_group;\n" ::: "memory");
    }
    __syncthreads();

    // ---- fused expansion: 128 b x 3 k x 256 t floats for this block ----
    for (int f = tid; f < 128 * 3 * (LCH / 4); f += 128) {
        int t4 = f & (LCH / 4 - 1);      // 0..63 (float4 index in t)
        int r  = f >> 6;
        int bq = r / 3;
        int k  = r - bq * 3;
        uint32_t wv = sb16[(k * 16 + (t4 >> 2)) * 128 + bq];
        int sh = (t4 & 3) * 4;
        float4 o;
        o.x = (float)((wv >> (sh + 0)) & 1u);
        o.y = (float)((wv >> (sh + 1)) & 1u);
        o.z = (float)((wv >> (sh + 2)) & 1u);
        o.w = (float)((wv >> (sh + 3)) & 1u);
        *(float4*)(out_s + ((size_t)(b0s + bq) * 3 + k) * TT + out_t0 + t4 * 4) = o;
    }
}

// ---------------------------------------------------------------------------
extern "C" void kernel_launch(void* const* d_in, const int* in_sizes, int n_in,
                              void* d_out, int out_size) {
    const float* x   = (const float*)d_in[0];
    // d_in[1] = y, unused by the reference outputs
    const float* w8  = (const float*)d_in[2];
    const float* w16 = (const float*)d_in[3];
    const float* w32 = (const float*)d_in[4];
    float* out = (float*)d_out;

    const int smem_scan = NBUF * ROWS * RPAD * 4 + KK * 16 * 128 * 2;  // 104448 B
    cudaFuncSetAttribute(scan_kernel, cudaFuncAttributeMaxDynamicSharedMemorySize, smem_scan);

    conv_kernel<<<dim3(TT / 64, BB / 32), 256>>>(x, w8, w16, w32, out);
    scan_kernel<<<NCH * 2, 128, smem_scan>>>(out, out + (size_t)BB * KK * TT);
}

// round 12
// speedup vs baseline: 1.1476x; 1.1476x over previous
#include <cuda_runtime.h>
#include <stdint.h>

#define BB 256
#define TT 32768
#define KK 3
#define ALPHA 0.95f
#define THETA 0.05f
#define LCH 256          // chunk length
#define NCH (TT / LCH)   // 128 chunks
#define WMAX 512         // max warmup steps
#define WS 32            // scan window steps (rows are full 128B lines)
#define ROWS 384         // 128 b x 3 k rows per scan block
#define NBUF 2           // smem ring depth

// ---------------------------------------------------------------------------
// Kernel 1: causal convs. Tile = 32 b x 64 t, 256 threads, 8 outputs/thread.
// Writes u ONLY to d_out [b][k][t]. FMA accumulation order identical to
// validated R3-R11 kernels (bit-identical u -> identical spikes).
// ---------------------------------------------------------------------------
__global__ void __launch_bounds__(256) conv_kernel(const float* __restrict__ x,
                                                   const float* __restrict__ w8,
                                                   const float* __restrict__ w16,
                                                   const float* __restrict__ w32,
                                                   float* __restrict__ u_out) {
    __shared__ float wf[64];   // flipped weights: [0:32)=w32, [32:48)=w16, [48:56)=w8
    __shared__ __align__(16) float buf[KK * 32 * 69];
    float (*xs)[100]    = reinterpret_cast<float (*)[100]>(buf);     // 32 x 100
    float (*us)[32][69] = reinterpret_cast<float (*)[32][69]>(buf);  // 3 x 32 x 69

    const int tid    = threadIdx.x;
    const int w      = tid >> 5;
    const int l      = tid & 31;
    const int tile_t = blockIdx.x * 64;
    const int b0     = blockIdx.y * 32;

    if (tid < 32)       wf[tid] = w32[31 - tid];
    else if (tid < 48)  wf[tid] = w16[47 - tid];
    else if (tid < 56)  wf[tid] = w8[55 - tid];

    // phase A (vectorized): xs[r][4*c4..] = x[b0+r][tile_t-32+4*c4..]
    {
        const int r  = 4 * w + (l >> 3);
        const int c4 = l & 7;
        const float4* xrow = (const float4*)(x + (size_t)(b0 + r) * TT + tile_t - 32);
        float4* xsrow = (float4*)&xs[r][0];
        if (tile_t == 0) {
            xsrow[c4] = make_float4(0.f, 0.f, 0.f, 0.f);   // left halo = zeros
        } else {
            xsrow[c4] = xrow[c4];
        }
        xsrow[c4 + 8]  = xrow[c4 + 8];
        xsrow[c4 + 16] = xrow[c4 + 16];
    }
    __syncthreads();

    // phase B: 8 outputs per thread; window via 10 LDS.128
    const int bl = l;
    const int tq = w * 8;
    float win[40];                      // win[i] = x[tile_t + tq + i - 32]
    {
        const float4* wrow = (const float4*)&xs[bl][tq];
#pragma unroll
        for (int i4 = 0; i4 < 10; i4++) {
            float4 v = wrow[i4];
            win[4 * i4 + 0] = v.x;
            win[4 * i4 + 1] = v.y;
            win[4 * i4 + 2] = v.z;
            win[4 * i4 + 3] = v.w;
        }
    }
    __syncthreads();   // xs dead; union reused as us

    float a32[8] = {0,0,0,0,0,0,0,0}, a16[8] = {0,0,0,0,0,0,0,0}, a8[8] = {0,0,0,0,0,0,0,0};
#pragma unroll
    for (int d = 0; d < 32; d++) {
        float wv = wf[d];
#pragma unroll
        for (int j = 0; j < 8; j++) a32[j] = fmaf(wv, win[32 + j - d], a32[j]);
    }
#pragma unroll
    for (int d = 0; d < 16; d++) {
        float wv = wf[32 + d];
#pragma unroll
        for (int j = 0; j < 8; j++) a16[j] = fmaf(wv, win[32 + j - d], a16[j]);
    }
#pragma unroll
    for (int d = 0; d < 8; d++) {
        float wv = wf[48 + d];
#pragma unroll
        for (int j = 0; j < 8; j++) a8[j] = fmaf(wv, win[32 + j - d], a8[j]);
    }
#pragma unroll
    for (int j = 0; j < 8; j++) {
        us[0][bl][tq + j] = a8[j];
        us[1][bl][tq + j] = a16[j];
        us[2][bl][tq + j] = a32[j];
    }
    __syncthreads();

    // phase D: u_out [b][k][t] (warp writes 128B rows)
#pragma unroll
    for (int bbq = 0; bbq < 4; bbq++) {
        int bb = w * 4 + bbq;
        float* orow = u_out + (size_t)(b0 + bb) * 3 * TT + tile_t;
#pragma unroll
        for (int k = 0; k < 3; k++)
#pragma unroll
            for (int h = 0; h < 2; h++)
                orow[(size_t)k * TT + 32 * h + l] = us[k][bb][32 * h + l];
    }
}

// ---------------------------------------------------------------------------
// Kernel 2: chunked WTA-LIF scan reading u_out directly. Window = 32 steps:
// tile [384 rows][128B] staged via cp.async into a 2-deep smem ring with a
// SW128-style XOR swizzle (16B seg s of row r stored at s ^ (r&7)).
// Consumer: thread tid owns rows 3*tid..3*tid+2; LDS.128 quad-bank =
// tg ^ (r&7), r = 3*lane+k -> each quad-bank hit exactly 4x => conflict-free.
// ---------------------------------------------------------------------------
__device__ __forceinline__ void lif_step(float& v0, float& v1, float& v2,
                                         float u0, float u1, float u2,
                                         bool& s0, bool& s1, bool& s2) {
    v0 = fmaf(ALPHA, v0, u0);
    v1 = fmaf(ALPHA, v1, u1);
    v2 = fmaf(ALPHA, v2, u2);
    // winner-take-all, argmax first-index tie-break, spike iff winner >= theta
    s0 = (v0 >= v1) & (v0 >= v2) & (v0 >= THETA);
    s1 = (v1 >  v0) & (v1 >= v2) & (v1 >= THETA);
    s2 = (v2 >  v0) & (v2 >  v1) & (v2 >= THETA);
    v0 = s0 ? v0 - THETA : v0;
    v1 = s1 ? v1 - THETA : v1;
    v2 = s2 ? v2 - THETA : v2;
}

extern __shared__ __align__(16) unsigned char smem_raw[];

__global__ void __launch_bounds__(128) scan_kernel(const float* __restrict__ u,
                                                   float* __restrict__ out_s) {
    float*    ub = (float*)smem_raw;                                   // [NBUF][ROWS][32] swizzled
    uint32_t* sb = (uint32_t*)(smem_raw + (size_t)NBUF * ROWS * WS * 4); // [KK][8][128]

    const int tid    = threadIdx.x;
    const int b0s    = (blockIdx.x & 1) * 128;
    const int c      = blockIdx.x >> 1;
    const int out_t0 = c * LCH;
    const int t0     = (out_t0 > WMAX) ? (out_t0 - WMAX) : 0;
    const int nw     = out_t0 - t0;        // warmup steps (0, 256, or 512)
    const int nww    = nw / WS;            // warmup windows (0, 8, or 16)
    const int nwT    = nww + LCH / WS;     // total windows (8, 16, or 24)

    const float* gbase = u + (size_t)b0s * 3 * TT + t0;   // + row*TT + t

    // --- async producer: window w's [384 x 128B] tile into ring slot w&1 ---
    auto issue_window = [&](int w) {
        float* dst = ub + (size_t)(w & 1) * ROWS * WS;
        const int tw = w * WS;
#pragma unroll
        for (int i = 0; i < 24; i++) {
            int e   = tid + 128 * i;       // 0..3071
            int r   = e >> 3;              // row 0..383
            int seg = e & 7;               // 16B segment within the 128B row
            const float* src = gbase + (size_t)r * TT + tw + 4 * seg;
            unsigned sdst = (unsigned)__cvta_generic_to_shared(
                dst + r * WS + ((seg ^ (r & 7)) << 2));
            asm volatile("cp.async.ca.shared.global [%0], [%1], 16;\n"
                         :: "r"(sdst), "l"(src) : "memory");
        }
    };

    issue_window(0); asm volatile("cp.async.commit_group;\n" ::: "memory");
    issue_window(1); asm volatile("cp.async.commit_group;\n" ::: "memory");

    const int r0  = 3 * tid;
    const int sw0 = r0 & 7, sw1 = (r0 + 1) & 7, sw2 = (r0 + 2) & 7;

    float v0 = 0.f, v1 = 0.f, v2 = 0.f;
    bool s0, s1, s2;

    // ---- warmup windows: no spike recording ----
    for (int w = 0; w < nww; w++) {
        asm volatile("cp.async.wait_group 1;\n" ::: "memory");
        __syncthreads();
        const float* t = ub + (size_t)(w & 1) * ROWS * WS;
#pragma unroll
        for (int tg = 0; tg < 8; tg++) {
            float4 a  = *(const float4*)(t + r0 * WS + ((tg ^ sw0) << 2));
            float4 bq = *(const float4*)(t + (r0 + 1) * WS + ((tg ^ sw1) << 2));
            float4 cq = *(const float4*)(t + (r0 + 2) * WS + ((tg ^ sw2) << 2));
            lif_step(v0, v1, v2, a.x, bq.x, cq.x, s0, s1, s2);
            lif_step(v0, v1, v2, a.y, bq.y, cq.y, s0, s1, s2);
            lif_step(v0, v1, v2, a.z, bq.z, cq.z, s0, s1, s2);
            lif_step(v0, v1, v2, a.w, bq.w, cq.w, s0, s1, s2);
        }
        __syncthreads();
        if (w + NBUF < nwT) issue_window(w + NBUF);
        asm volatile("cp.async.commit_group;\n" ::: "memory");
    }

    // ---- main windows: record spikes (uint32 mask per window) ----
    for (int mw = 0; mw < LCH / WS; mw++) {
        const int w = nww + mw;
        asm volatile("cp.async.wait_group 1;\n" ::: "memory");
        __syncthreads();
        const float* t = ub + (size_t)(w & 1) * ROWS * WS;
        uint32_t m0 = 0, m1 = 0, m2 = 0;
#pragma unroll
        for (int tg = 0; tg < 8; tg++) {
            float4 a  = *(const float4*)(t + r0 * WS + ((tg ^ sw0) << 2));
            float4 bq = *(const float4*)(t + (r0 + 1) * WS + ((tg ^ sw1) << 2));
            float4 cq = *(const float4*)(t + (r0 + 2) * WS + ((tg ^ sw2) << 2));
#pragma unroll
            for (int j = 0; j < 4; j++) {
                float u0 = (j == 0) ? a.x  : (j == 1) ? a.y  : (j == 2) ? a.z  : a.w;
                float u1 = (j == 0) ? bq.x : (j == 1) ? bq.y : (j == 2) ? bq.z : bq.w;
                float u2 = (j == 0) ? cq.x : (j == 1) ? cq.y : (j == 2) ? cq.z : cq.w;
                lif_step(v0, v1, v2, u0, u1, u2, s0, s1, s2);
                const uint32_t bit = 1u << (tg * 4 + j);
                if (s0) m0 |= bit;
                if (s1) m1 |= bit;
                if (s2) m2 |= bit;
            }
        }
        sb[(0 * 8 + mw) * 128 + tid] = m0;
        sb[(1 * 8 + mw) * 128 + tid] = m1;
        sb[(2 * 8 + mw) * 128 + tid] = m2;
        __syncthreads();
        if (w + NBUF < nwT) issue_window(w + NBUF);
        asm volatile("cp.async.commit_group;\n" ::: "memory");
    }
    __syncthreads();

    // ---- fused expansion: 128 b x 3 k x 256 t floats for this block ----
    for (int f = tid; f < 128 * 3 * (LCH / 4); f += 128) {
        int t4 = f & (LCH / 4 - 1);      // 0..63 (float4 index in t)
        int r  = f >> 6;
        int bq = r / 3;
        int k  = r - bq * 3;
        uint32_t wv = sb[(k * 8 + (t4 >> 3)) * 128 + bq];
        int sh = (t4 & 7) * 4;
        float4 o;
        o.x = (float)((wv >> (sh + 0)) & 1u);
        o.y = (float)((wv >> (sh + 1)) & 1u);
        o.z = (float)((wv >> (sh + 2)) & 1u);
        o.w = (float)((wv >> (sh + 3)) & 1u);
        *(float4*)(out_s + ((size_t)(b0s + bq) * 3 + k) * TT + out_t0 + t4 * 4) = o;
    }
}

// ---------------------------------------------------------------------------
extern "C" void kernel_launch(void* const* d_in, const int* in_sizes, int n_in,
                              void* d_out, int out_size) {
    const float* x   = (const float*)d_in[0];
    // d_in[1] = y, unused by the reference outputs
    const float* w8  = (const float*)d_in[2];
    const float* w16 = (const float*)d_in[3];
    const float* w32 = (const float*)d_in[4];
    float* out = (float*)d_out;

    const int smem_scan = NBUF * ROWS * WS * 4 + KK * 8 * 128 * 4;  // 110592 B
    cudaFuncSetAttribute(scan_kernel, cudaFuncAttributeMaxDynamicSharedMemorySize, smem_scan);

    conv_kernel<<<dim3(TT / 64, BB / 32), 256>>>(x, w8, w16, w32, out);
    scan_kernel<<<NCH * 2, 128, smem_scan>>>(out, out + (size_t)BB * KK * TT);
}

// round 13
// speedup vs baseline: 1.1934x; 1.0399x over previous
#include <cuda_runtime.h>
#include <stdint.h>

#define BB 256
#define TT 32768
#define TT4 (TT / 4)
#define KK 3
#define ALPHA 0.95f
#define THETA 0.05f
#define LCH 128          // chunk length
#define NCH (TT / LCH)   // 256 chunks
#define WMAX 512         // max warmup steps
#define G 4              // float4 groups (4 steps each) in flight per plane

// scratch: u in blocked transpose [k][t/4][b][4] + pad covering the register
// pipeline's worst-case overrun (last chunk reads a few groups past TT4)
__device__ float g_uB[KK * TT4 * BB * 4 + 131072];

// ---------------------------------------------------------------------------
// Kernel 1: causal convs. Tile = 32 b x 64 t, 256 threads, 8 outputs/thread.
// Writes u to d_out [b][k][t] and to g_uB [k][t/4][b][4] (both coalesced).
// FMA accumulation order identical to validated R3-R12 kernels (bit-identical u).
// ---------------------------------------------------------------------------
__global__ void __launch_bounds__(256) conv_kernel(const float* __restrict__ x,
                                                   const float* __restrict__ w8,
                                                   const float* __restrict__ w16,
                                                   const float* __restrict__ w32,
                                                   float* __restrict__ u_out) {
    __shared__ float wf[64];   // flipped weights: [0:32)=w32, [32:48)=w16, [48:56)=w8
    __shared__ __align__(16) float buf[KK * 32 * 69];
    float (*xs)[100]    = reinterpret_cast<float (*)[100]>(buf);     // 32 x 100
    float (*us)[32][69] = reinterpret_cast<float (*)[32][69]>(buf);  // 3 x 32 x 69

    const int tid    = threadIdx.x;
    const int w      = tid >> 5;
    const int l      = tid & 31;
    const int tile_t = blockIdx.x * 64;
    const int b0     = blockIdx.y * 32;

    if (tid < 32)       wf[tid] = w32[31 - tid];
    else if (tid < 48)  wf[tid] = w16[47 - tid];
    else if (tid < 56)  wf[tid] = w8[55 - tid];

    // phase A (vectorized): xs[r][4*c4..] = x[b0+r][tile_t-32+4*c4..]
    {
        const int r  = 4 * w + (l >> 3);
        const int c4 = l & 7;
        const float4* xrow = (const float4*)(x + (size_t)(b0 + r) * TT + tile_t - 32);
        float4* xsrow = (float4*)&xs[r][0];
        if (tile_t == 0) {
            xsrow[c4] = make_float4(0.f, 0.f, 0.f, 0.f);   // left halo = zeros
        } else {
            xsrow[c4] = xrow[c4];
        }
        xsrow[c4 + 8]  = xrow[c4 + 8];
        xsrow[c4 + 16] = xrow[c4 + 16];
    }
    __syncthreads();

    // phase B: 8 outputs per thread; window via 10 LDS.128
    const int bl = l;
    const int tq = w * 8;
    float win[40];                      // win[i] = x[tile_t + tq + i - 32]
    {
        const float4* wrow = (const float4*)&xs[bl][tq];
#pragma unroll
        for (int i4 = 0; i4 < 10; i4++) {
            float4 v = wrow[i4];
            win[4 * i4 + 0] = v.x;
            win[4 * i4 + 1] = v.y;
            win[4 * i4 + 2] = v.z;
            win[4 * i4 + 3] = v.w;
        }
    }
    __syncthreads();   // xs dead; union reused as us

    float a32[8] = {0,0,0,0,0,0,0,0}, a16[8] = {0,0,0,0,0,0,0,0}, a8[8] = {0,0,0,0,0,0,0,0};
#pragma unroll
    for (int d = 0; d < 32; d++) {
        float wv = wf[d];
#pragma unroll
        for (int j = 0; j < 8; j++) a32[j] = fmaf(wv, win[32 + j - d], a32[j]);
    }
#pragma unroll
    for (int d = 0; d < 16; d++) {
        float wv = wf[32 + d];
#pragma unroll
        for (int j = 0; j < 8; j++) a16[j] = fmaf(wv, win[32 + j - d], a16[j]);
    }
#pragma unroll
    for (int d = 0; d < 8; d++) {
        float wv = wf[48 + d];
#pragma unroll
        for (int j = 0; j < 8; j++) a8[j] = fmaf(wv, win[32 + j - d], a8[j]);
    }
#pragma unroll
    for (int j = 0; j < 8; j++) {
        us[0][bl][tq + j] = a8[j];
        us[1][bl][tq + j] = a16[j];
        us[2][bl][tq + j] = a32[j];
    }
    __syncthreads();

    // phase D: u_out [b][k][t] (warp writes 128B rows)
#pragma unroll
    for (int bbq = 0; bbq < 4; bbq++) {
        int bb = w * 4 + bbq;
        float* orow = u_out + (size_t)(b0 + bb) * 3 * TT + tile_t;
#pragma unroll
        for (int k = 0; k < 3; k++)
#pragma unroll
            for (int h = 0; h < 2; h++)
                orow[(size_t)k * TT + 32 * h + l] = us[k][bb][32 * h + l];
    }
    // phase E: g_uB [k][tg][b][4] (lane = b, warp writes 512B chunks)
#pragma unroll
    for (int r = 0; r < 6; r++) {
        int row = w + r * 8;          // 0..47 = k*16 + tgl
        int k   = row >> 4;
        int tgl = row & 15;
        float4 v;
        v.x = us[k][l][tgl * 4 + 0];
        v.y = us[k][l][tgl * 4 + 1];
        v.z = us[k][l][tgl * 4 + 2];
        v.w = us[k][l][tgl * 4 + 3];
        *(float4*)&g_uB[(((size_t)k * TT4 + (tile_t >> 2) + tgl) * BB + b0 + l) * 4] = v;
    }
}

// ---------------------------------------------------------------------------
// Kernel 2: chunked WTA-LIF scan + fused spike expansion. Reads g_uB (warp =
// 512B coalesced). LCH=128 -> 2048 warps (3.46/SMSP): multi-warp latency
// hiding; register pipeline G=4 (16-step distance, slot index compile-time
// via gg&3 inside fully-unrolled 32-step windows).
// ---------------------------------------------------------------------------
__device__ __forceinline__ void lif_step(float& v0, float& v1, float& v2,
                                         float u0, float u1, float u2,
                                         bool& s0, bool& s1, bool& s2) {
    v0 = fmaf(ALPHA, v0, u0);
    v1 = fmaf(ALPHA, v1, u1);
    v2 = fmaf(ALPHA, v2, u2);
    // winner-take-all, argmax first-index tie-break, spike iff winner >= theta
    s0 = (v0 >= v1) & (v0 >= v2) & (v0 >= THETA);
    s1 = (v1 >  v0) & (v1 >= v2) & (v1 >= THETA);
    s2 = (v2 >  v0) & (v2 >  v1) & (v2 >= THETA);
    v0 = s0 ? v0 - THETA : v0;
    v1 = s1 ? v1 - THETA : v1;
    v2 = s2 ? v2 - THETA : v2;
}

__global__ void __launch_bounds__(128, 3) scan_kernel(float* __restrict__ out_s) {
    __shared__ uint32_t sb[KK][LCH / 32][128];   // per-thread masks [k][window][b], 6 KB

    const int tid    = threadIdx.x;
    const int b0s    = (blockIdx.x & 1) * 128;
    const int c      = blockIdx.x >> 1;
    const int b      = b0s + tid;
    const int out_t0 = c * LCH;
    const int t0     = (out_t0 > WMAX) ? (out_t0 - WMAX) : 0;
    const int nw     = out_t0 - t0;      // warmup steps (0..512, multiple of 128)
    const int gb0    = t0 >> 2;          // starting group index

    // plane pointers in float4 units; group stride = BB float4s (4 KB)
    const float4* p0 = (const float4*)g_uB + ((size_t)0 * TT4 + gb0) * BB + b;
    const float4* p1 = (const float4*)g_uB + ((size_t)1 * TT4 + gb0) * BB + b;
    const float4* p2 = (const float4*)g_uB + ((size_t)2 * TT4 + gb0) * BB + b;

    float4 q0[G], q1[G], q2[G];
#pragma unroll
    for (int i = 0; i < G; i++) {
        q0[i] = __ldg(p0 + (size_t)i * BB);
        q1[i] = __ldg(p1 + (size_t)i * BB);
        q2[i] = __ldg(p2 + (size_t)i * BB);
    }

    float v0 = 0.f, v1 = 0.f, v2 = 0.f;
    bool s0, s1, s2;

    // ---- warmup: windows of 8 groups (32 steps), slot = gg & 3 ----
    const int nww = nw >> 5;             // 0..16 windows
    for (int ww = 0; ww < nww; ww++) {
#pragma unroll
        for (int gg = 0; gg < 8; gg++) {
            const int s = gg & (G - 1);
            float4 a = q0[s], bq = q1[s], cq = q2[s];
            q0[s] = __ldg(p0 + (size_t)(gg + G) * BB);
            q1[s] = __ldg(p1 + (size_t)(gg + G) * BB);
            q2[s] = __ldg(p2 + (size_t)(gg + G) * BB);
            lif_step(v0, v1, v2, a.x, bq.x, cq.x, s0, s1, s2);
            lif_step(v0, v1, v2, a.y, bq.y, cq.y, s0, s1, s2);
            lif_step(v0, v1, v2, a.z, bq.z, cq.z, s0, s1, s2);
            lif_step(v0, v1, v2, a.w, bq.w, cq.w, s0, s1, s2);
        }
        p0 += (size_t)8 * BB; p1 += (size_t)8 * BB; p2 += (size_t)8 * BB;
    }

    // ---- main: LCH/32 windows of 32 steps; thread-local bit packing ----
    for (int w32 = 0; w32 < LCH / 32; w32++) {
        uint32_t m0 = 0, m1 = 0, m2 = 0;
#pragma unroll
        for (int gg = 0; gg < 8; gg++) {
            const int s = gg & (G - 1);
            float4 a = q0[s], bq = q1[s], cq = q2[s];
            q0[s] = __ldg(p0 + (size_t)(gg + G) * BB);
            q1[s] = __ldg(p1 + (size_t)(gg + G) * BB);
            q2[s] = __ldg(p2 + (size_t)(gg + G) * BB);
#pragma unroll
            for (int j = 0; j < 4; j++) {
                float u0 = (j == 0) ? a.x  : (j == 1) ? a.y  : (j == 2) ? a.z  : a.w;
                float u1 = (j == 0) ? bq.x : (j == 1) ? bq.y : (j == 2) ? bq.z : bq.w;
                float u2 = (j == 0) ? cq.x : (j == 1) ? cq.y : (j == 2) ? cq.z : cq.w;
                lif_step(v0, v1, v2, u0, u1, u2, s0, s1, s2);
                const uint32_t bit = 1u << (gg * 4 + j);
                if (s0) m0 |= bit;
                if (s1) m1 |= bit;
                if (s2) m2 |= bit;
            }
        }
        p0 += (size_t)8 * BB; p1 += (size_t)8 * BB; p2 += (size_t)8 * BB;
        sb[0][w32][tid] = m0;
        sb[1][w32][tid] = m1;
        sb[2][w32][tid] = m2;
    }
    __syncthreads();

    // ---- fused expansion: 128 b x 3 k x 128 t floats for this block ----
    for (int f = tid; f < 128 * 3 * (LCH / 4); f += 128) {
        int t4 = f & (LCH / 4 - 1);      // 0..31 (float4 index in t)
        int r  = f >> 5;
        int bq = r / 3;
        int k  = r - bq * 3;
        uint32_t wv = sb[k][t4 >> 3][bq];
        int sh = (t4 & 7) * 4;
        float4 o;
        o.x = (float)((wv >> (sh + 0)) & 1u);
        o.y = (float)((wv >> (sh + 1)) & 1u);
        o.z = (float)((wv >> (sh + 2)) & 1u);
        o.w = (float)((wv >> (sh + 3)) & 1u);
        *(float4*)(out_s + ((size_t)(b0s + bq) * 3 + k) * TT + out_t0 + t4 * 4) = o;
    }
}

// ---------------------------------------------------------------------------
extern "C" void kernel_launch(void* const* d_in, const int* in_sizes, int n_in,
                              void* d_out, int out_size) {
    const float* x   = (const float*)d_in[0];
    // d_in[1] = y, unused by the reference outputs
    const float* w8  = (const float*)d_in[2];
    const float* w16 = (const float*)d_in[3];
    const float* w32 = (const float*)d_in[4];
    float* out = (float*)d_out;

    conv_kernel<<<dim3(TT / 64, BB / 32), 256>>>(x, w8, w16, w32, out);
    scan_kernel<<<NCH * 2, 128>>>(out + (size_t)BB * KK * TT);
}

// round 14
// speedup vs baseline: 1.4558x; 1.2199x over previous
#include <cuda_runtime.h>
#include <stdint.h>

#define BB 256
#define TT 32768
#define TT4 (TT / 4)
#define KK 3
#define ALPHA 0.95f
#define THETA 0.05f
#define LCH 256          // chunk length
#define NCH (TT / LCH)   // 128 chunks
#define WMAX 512         // max warmup steps
#define G 8              // float4 groups (4 steps each) in flight per plane

typedef unsigned long long ull;

// scratch: u in blocked transpose [k][t/4][b][4] + pad covering the register
// pipeline's worst-case overrun (last chunk reads ~71 groups past TT4)
__device__ float g_uB[KK * TT4 * BB * 4 + 131072];

#define PACK2(dst, lo, hi) \
    asm("mov.b64 %0, {%1, %2};" : "=l"(dst) : "f"(lo), "f"(hi))
#define UNPACK2(lo, hi, src) \
    asm("mov.b64 {%0, %1}, %2;" : "=f"(lo), "=f"(hi) : "l"(src))
#define FMA2(acc, a, b) \
    asm("fma.rn.f32x2 %0, %1, %2, %0;" : "+l"(acc) : "l"(a), "l"(b))

// ---------------------------------------------------------------------------
// Kernel 1: causal convs. Tile = 32 b x 64 t, 256 threads, 8 outputs/thread.
// FFMA2 (fma.rn.f32x2) pairs outputs (2p, 2p+1): per-lane IEEE fma with the
// same accumulation order as R3-R13 -> u bit-identical. Writes u to d_out
// [b][k][t] and g_uB [k][t/4][b][4].
// ---------------------------------------------------------------------------
__global__ void __launch_bounds__(256) conv_kernel(const float* __restrict__ x,
                                                   const float* __restrict__ w8,
                                                   const float* __restrict__ w16,
                                                   const float* __restrict__ w32,
                                                   float* __restrict__ u_out) {
    __shared__ __align__(8) float2 wf2[64]; // duplicated flipped weights
    __shared__ __align__(16) float buf[KK * 32 * 69];
    float (*xs)[100]    = reinterpret_cast<float (*)[100]>(buf);     // 32 x 100
    float (*us)[32][69] = reinterpret_cast<float (*)[32][69]>(buf);  // 3 x 32 x 69

    const int tid    = threadIdx.x;
    const int w      = tid >> 5;
    const int l      = tid & 31;
    const int tile_t = blockIdx.x * 64;
    const int b0     = blockIdx.y * 32;

    if (tid < 32)       { float v = w32[31 - tid];  wf2[tid] = make_float2(v, v); }
    else if (tid < 48)  { float v = w16[47 - tid];  wf2[tid] = make_float2(v, v); }
    else if (tid < 56)  { float v = w8[55 - tid];   wf2[tid] = make_float2(v, v); }

    // phase A (vectorized): xs[r][4*c4..] = x[b0+r][tile_t-32+4*c4..]
    {
        const int r  = 4 * w + (l >> 3);
        const int c4 = l & 7;
        const float4* xrow = (const float4*)(x + (size_t)(b0 + r) * TT + tile_t - 32);
        float4* xsrow = (float4*)&xs[r][0];
        if (tile_t == 0) {
            xsrow[c4] = make_float4(0.f, 0.f, 0.f, 0.f);   // left halo = zeros
        } else {
            xsrow[c4] = xrow[c4];
        }
        xsrow[c4 + 8]  = xrow[c4 + 8];
        xsrow[c4 + 16] = xrow[c4 + 16];
    }
    __syncthreads();

    // phase B: window win[i] = x[tile_t + tq + i - 32], i in [0,40), packed:
    //   E[i] = (win[2i], win[2i+1])   i = 0..19   (natural float4 halves)
    //   O[i] = (win[2i+1], win[2i+2]) i = 0..18
    const int bl = l;
    const int tq = w * 8;
    ull E[20], O[19];
    {
        const float4* wrow = (const float4*)&xs[bl][tq];
        float prev_w = 0.0f;
#pragma unroll
        for (int i4 = 0; i4 < 10; i4++) {
            float4 v = wrow[i4];
            PACK2(E[2 * i4],     v.x, v.y);
            PACK2(E[2 * i4 + 1], v.z, v.w);
            if (i4 > 0) PACK2(O[2 * i4 - 1], prev_w, v.x);
            if (i4 < 10) PACK2(O[2 * i4], v.y, v.z);
            prev_w = v.w;
        }
    }
    __syncthreads();   // xs dead; union reused as us

    // acc pairs: Axx[p] covers outputs (j=2p, j=2p+1)
    ull A32[4] = {0,0,0,0}, A16[4] = {0,0,0,0}, A8[4] = {0,0,0,0};
    const ull* wfp = (const ull*)wf2;

#pragma unroll
    for (int d = 0; d < 32; d++) {
        ull wv = wfp[d];
        const int base = 32 - d;     // addend pair start = win[base + 2p]
#pragma unroll
        for (int p = 0; p < 4; p++) {
            if ((base & 1) == 0) { FMA2(A32[p], wv, E[(base >> 1) + p]); }
            else                 { FMA2(A32[p], wv, O[((base - 1) >> 1) + p]); }
        }
    }
#pragma unroll
    for (int d = 0; d < 16; d++) {
        ull wv = wfp[32 + d];
        const int base = 32 - d;
#pragma unroll
        for (int p = 0; p < 4; p++) {
            if ((base & 1) == 0) { FMA2(A16[p], wv, E[(base >> 1) + p]); }
            else                 { FMA2(A16[p], wv, O[((base - 1) >> 1) + p]); }
        }
    }
#pragma unroll
    for (int d = 0; d < 8; d++) {
        ull wv = wfp[48 + d];
        const int base = 32 - d;
#pragma unroll
        for (int p = 0; p < 4; p++) {
            if ((base & 1) == 0) { FMA2(A8[p], wv, E[(base >> 1) + p]); }
            else                 { FMA2(A8[p], wv, O[((base - 1) >> 1) + p]); }
        }
    }

#pragma unroll
    for (int p = 0; p < 4; p++) {
        float lo, hi;
        UNPACK2(lo, hi, A8[p]);
        us[0][bl][tq + 2 * p] = lo;  us[0][bl][tq + 2 * p + 1] = hi;
        UNPACK2(lo, hi, A16[p]);
        us[1][bl][tq + 2 * p] = lo;  us[1][bl][tq + 2 * p + 1] = hi;
        UNPACK2(lo, hi, A32[p]);
        us[2][bl][tq + 2 * p] = lo;  us[2][bl][tq + 2 * p + 1] = hi;
    }
    __syncthreads();

    // phase D: u_out [b][k][t] (warp writes 128B rows)
#pragma unroll
    for (int bbq = 0; bbq < 4; bbq++) {
        int bb = w * 4 + bbq;
        float* orow = u_out + (size_t)(b0 + bb) * 3 * TT + tile_t;
#pragma unroll
        for (int k = 0; k < 3; k++)
#pragma unroll
            for (int h = 0; h < 2; h++)
                orow[(size_t)k * TT + 32 * h + l] = us[k][bb][32 * h + l];
    }
    // phase E: g_uB [k][tg][b][4] (lane = b, warp writes 512B chunks)
#pragma unroll
    for (int r = 0; r < 6; r++) {
        int row = w + r * 8;          // 0..47 = k*16 + tgl
        int k   = row >> 4;
        int tgl = row & 15;
        float4 v;
        v.x = us[k][l][tgl * 4 + 0];
        v.y = us[k][l][tgl * 4 + 1];
        v.z = us[k][l][tgl * 4 + 2];
        v.w = us[k][l][tgl * 4 + 3];
        *(float4*)&g_uB[(((size_t)k * TT4 + (tile_t >> 2) + tgl) * BB + b0 + l) * 4] = v;
    }
}

// ---------------------------------------------------------------------------
// Kernel 2: chunked WTA-LIF scan + fused spike expansion (R10 exact: LCH=256,
// G=8 register pipeline, 32-step unrolled windows, thread-local bit packing).
// ---------------------------------------------------------------------------
__device__ __forceinline__ void lif_step(float& v0, float& v1, float& v2,
                                         float u0, float u1, float u2,
                                         bool& s0, bool& s1, bool& s2) {
    v0 = fmaf(ALPHA, v0, u0);
    v1 = fmaf(ALPHA, v1, u1);
    v2 = fmaf(ALPHA, v2, u2);
    // winner-take-all, argmax first-index tie-break, spike iff winner >= theta
    s0 = (v0 >= v1) & (v0 >= v2) & (v0 >= THETA);
    s1 = (v1 >  v0) & (v1 >= v2) & (v1 >= THETA);
    s2 = (v2 >  v0) & (v2 >  v1) & (v2 >= THETA);
    v0 = s0 ? v0 - THETA : v0;
    v1 = s1 ? v1 - THETA : v1;
    v2 = s2 ? v2 - THETA : v2;
}

__global__ void __launch_bounds__(128) scan_kernel(float* __restrict__ out_s) {
    __shared__ uint32_t sb[KK][LCH / 32][128];   // per-thread masks [k][window][b], 12 KB

    const int tid    = threadIdx.x;
    const int b0s    = (blockIdx.x & 1) * 128;
    const int c      = blockIdx.x >> 1;
    const int b      = b0s + tid;
    const int out_t0 = c * LCH;
    const int t0     = (out_t0 > WMAX) ? (out_t0 - WMAX) : 0;
    const int nw     = out_t0 - t0;      // warmup steps (0, 256, or 512)
    const int gb0    = t0 >> 2;          // starting group index

    // plane pointers in float4 units; group stride = BB float4s (4 KB)
    const float4* p0 = (const float4*)g_uB + ((size_t)0 * TT4 + gb0) * BB + b;
    const float4* p1 = (const float4*)g_uB + ((size_t)1 * TT4 + gb0) * BB + b;
    const float4* p2 = (const float4*)g_uB + ((size_t)2 * TT4 + gb0) * BB + b;

    float4 q0[G], q1[G], q2[G];
#pragma unroll
    for (int i = 0; i < G; i++) {
        q0[i] = __ldg(p0 + (size_t)i * BB);
        q1[i] = __ldg(p1 + (size_t)i * BB);
        q2[i] = __ldg(p2 + (size_t)i * BB);
    }

    float v0 = 0.f, v1 = 0.f, v2 = 0.f;
    bool s0, s1, s2;

    // ---- warmup: windows of 8 groups (32 steps) ----
    const int nww = nw >> 5;             // 0, 8, or 16 windows
    for (int ww = 0; ww < nww; ww++) {
#pragma unroll
        for (int gg = 0; gg < 8; gg++) {
            float4 a = q0[gg], bq = q1[gg], cq = q2[gg];
            q0[gg] = __ldg(p0 + (size_t)(gg + G) * BB);
            q1[gg] = __ldg(p1 + (size_t)(gg + G) * BB);
            q2[gg] = __ldg(p2 + (size_t)(gg + G) * BB);
            lif_step(v0, v1, v2, a.x, bq.x, cq.x, s0, s1, s2);
            lif_step(v0, v1, v2, a.y, bq.y, cq.y, s0, s1, s2);
            lif_step(v0, v1, v2, a.z, bq.z, cq.z, s0, s1, s2);
            lif_step(v0, v1, v2, a.w, bq.w, cq.w, s0, s1, s2);
        }
        p0 += (size_t)8 * BB; p1 += (size_t)8 * BB; p2 += (size_t)8 * BB;
    }

    // ---- main: 8 windows of 32 steps; thread-local bit packing ----
    for (int w32 = 0; w32 < LCH / 32; w32++) {
        uint32_t m0 = 0, m1 = 0, m2 = 0;
#pragma unroll
        for (int gg = 0; gg < 8; gg++) {
            float4 a = q0[gg], bq = q1[gg], cq = q2[gg];
            q0[gg] = __ldg(p0 + (size_t)(gg + G) * BB);
            q1[gg] = __ldg(p1 + (size_t)(gg + G) * BB);
            q2[gg] = __ldg(p2 + (size_t)(gg + G) * BB);
#pragma unroll
            for (int j = 0; j < 4; j++) {
                float u0 = (j == 0) ? a.x  : (j == 1) ? a.y  : (j == 2) ? a.z  : a.w;
                float u1 = (j == 0) ? bq.x : (j == 1) ? bq.y : (j == 2) ? bq.z : bq.w;
                float u2 = (j == 0) ? cq.x : (j == 1) ? cq.y : (j == 2) ? cq.z : cq.w;
                lif_step(v0, v1, v2, u0, u1, u2, s0, s1, s2);
                const uint32_t bit = 1u << (gg * 4 + j);
                if (s0) m0 |= bit;
                if (s1) m1 |= bit;
                if (s2) m2 |= bit;
            }
        }
        p0 += (size_t)8 * BB; p1 += (size_t)8 * BB; p2 += (size_t)8 * BB;
        sb[0][w32][tid] = m0;
        sb[1][w32][tid] = m1;
        sb[2][w32][tid] = m2;
    }
    __syncthreads();

    // ---- fused expansion: 128 b x 3 k x 256 t floats for this block ----
    for (int f = tid; f < 128 * 3 * (LCH / 4); f += 128) {
        int t4 = f & (LCH / 4 - 1);
        int r  = f >> 6;
        int bq = r / 3;
        int k  = r - bq * 3;
        uint32_t wv = sb[k][t4 >> 3][bq];
        int sh = (t4 & 7) * 4;
        float4 o;
        o.x = (float)((wv >> (sh + 0)) & 1u);
        o.y = (float)((wv >> (sh + 1)) & 1u);
        o.z = (float)((wv >> (sh + 2)) & 1u);
        o.w = (float)((wv >> (sh + 3)) & 1u);
        *(float4*)(out_s + ((size_t)(b0s + bq) * 3 + k) * TT + out_t0 + t4 * 4) = o;
    }
}

// ---------------------------------------------------------------------------
extern "C" void kernel_launch(void* const* d_in, const int* in_sizes, int n_in,
                              void* d_out, int out_size) {
    const float* x   = (const float*)d_in[0];
    // d_in[1] = y, unused by the reference outputs
    const float* w8  = (const float*)d_in[2];
    const float* w16 = (const float*)d_in[3];
    const float* w32 = (const float*)d_in[4];
    float* out = (float*)d_out;

    conv_kernel<<<dim3(TT / 64, BB / 32), 256>>>(x, w8, w16, w32, out);
    scan_kernel<<<NCH * 2, 128>>>(out + (size_t)BB * KK * TT);
}